// round 1
// baseline (speedup 1.0000x reference)
#include <cuda_runtime.h>
#include <cuda_bf16.h>

#define VOCAB  20000
#define TOPK   8
#define GLOVE  300
#define OUTC   100
#define NLAB   8
#define ROWS   16                    // 2*TOPK rows of 300 after reshape
#define FACT_PER_V (TOPK * 2 * GLOVE)  // 4800 floats per vocab entry

// Scratch (static __device__ — no allocation)
__device__ float g_proj[VOCAB * OUTC];   // per-vocab projected vector (8 MB)
__device__ float g_wt[GLOVE * OUTC];     // W transposed: Wt[c*100 + o]
__device__ int   g_used[VOCAB];          // per-launch usage flags

// ---------------------------------------------------------------------------
// K0: clear usage flags + transpose W (runs every launch; graph-replayed)
// ---------------------------------------------------------------------------
__global__ void k_clear_wt(const float* __restrict__ W) {
    int i = blockIdx.x * blockDim.x + threadIdx.x;
    if (i < VOCAB) g_used[i] = 0;
    if (i < GLOVE * OUTC) {
        int c = i / OUTC, o = i % OUTC;
        g_wt[i] = W[o * GLOVE + c];     // uncoalesced read, 30K elems, negligible
    }
}

// ---------------------------------------------------------------------------
// K1: mark used vocab entries (benign write races)
// ---------------------------------------------------------------------------
__global__ void k_mark(const int* __restrict__ labels, int n) {
    int i = blockIdx.x * blockDim.x + threadIdx.x;
    if (i < n) g_used[labels[i]] = 1;
}

// ---------------------------------------------------------------------------
// K2: for each USED vocab entry v:
//       s[c]     = sum_{r<16} fact[v][r*300 + c]           (streams 19.2KB)
//       proj[v][o] = sum_c Wt[c][o] * s[c]                 (30K FMA, Wt L1-hot)
// One block per v, 320 threads.
// ---------------------------------------------------------------------------
__global__ __launch_bounds__(320) void k_project(const float* __restrict__ fact) {
    __shared__ float sm[GLOVE];
    __shared__ float ps[3 * OUTC];
    const int v = blockIdx.x;
    if (!g_used[v]) return;

    const int t = threadIdx.x;
    const float* __restrict__ f = fact + (size_t)v * FACT_PER_V;

    // Phase 1: row-sum. Threads 0..299 each own one channel c; 16 coalesced
    // strided loads, fully unrolled -> MLP 16 per thread.
    if (t < GLOVE) {
        float s = 0.f;
        #pragma unroll
        for (int r = 0; r < ROWS; r++) s += f[r * GLOVE + t];
        sm[t] = s;
    }
    __syncthreads();

    // Phase 2: projection with transposed W -> contiguous 400B loads per c.
    // 300 threads: o = t%100 (contiguous within warp), seg = t/100 splits c.
    if (t < 3 * OUTC) {
        const int o = t % OUTC;
        const int seg = t / OUTC;
        const int cbase = seg * 100;
        float acc = 0.f;
        #pragma unroll 4
        for (int c = 0; c < 100; c++)
            acc += g_wt[(cbase + c) * OUTC + o] * sm[cbase + c];
        ps[t] = acc;
    }
    __syncthreads();
    if (t < OUTC)
        g_proj[v * OUTC + t] = ps[t] + ps[OUTC + t] + ps[2 * OUTC + t];
}

// ---------------------------------------------------------------------------
// K3: per token: y[o] = (sum_{8 labels} proj[label][o]) / 128 + b[o]
// One block per token; proj table is L2-hot (8 MB).
// ---------------------------------------------------------------------------
__global__ __launch_bounds__(128) void k_out(const int* __restrict__ labels,
                                             const float* __restrict__ bias,
                                             float* __restrict__ out) {
    __shared__ int lab[NLAB];
    const int token = blockIdx.x;
    const int t = threadIdx.x;
    if (t < NLAB) lab[t] = labels[token * NLAB + t];
    __syncthreads();
    if (t < OUTC) {
        float acc = 0.f;
        #pragma unroll
        for (int j = 0; j < NLAB; j++)
            acc += g_proj[lab[j] * OUTC + t];   // 400B coalesced per label
        out[token * OUTC + t] = acc * (1.0f / (NLAB * ROWS)) + bias[t];
    }
}

// ---------------------------------------------------------------------------
extern "C" void kernel_launch(void* const* d_in, const int* in_sizes, int n_in,
                              void* d_out, int out_size) {
    const int*   labels = (const int*)d_in[0];    // [32,128,8] int32
    const float* fact   = (const float*)d_in[1];  // [20000,8,600] f32
    const float* W      = (const float*)d_in[2];  // [100,300] f32
    const float* bias   = (const float*)d_in[3];  // [100] f32
    float* out = (float*)d_out;                   // [32,128,100] f32

    const int n_labels_total = in_sizes[0];       // 32768
    const int n_tokens = n_labels_total / NLAB;   // 4096

    k_clear_wt<<<(GLOVE * OUTC + 255) / 256, 256>>>(W);
    k_mark<<<(n_labels_total + 255) / 256, 256>>>(labels, n_labels_total);
    k_project<<<VOCAB, 320>>>(fact);
    k_out<<<n_tokens, 128>>>(labels, bias, out);
}